// round 7
// baseline (speedup 1.0000x reference)
#include <cuda_runtime.h>

// Problem constants
#define BC_C   9
#define BC_FR  64
#define BC_T   64
#define BC_P   4
#define BC_E   192
#define BC_NF  16
#define BC_NT  16

#define W_ROW_PAD 68   // 64 floats of W per e-quad + 4 pad -> conflict-free LDS.128

using u64 = unsigned long long;

__device__ __forceinline__ u64 pack2(float lo, float hi) {
    u64 r;
    asm("mov.b64 %0, {%1, %2};" : "=l"(r) : "f"(lo), "f"(hi));
    return r;
}
__device__ __forceinline__ void unpack2(u64 v, float& lo, float& hi) {
    asm("mov.b64 {%0, %1}, %2;" : "=f"(lo), "=f"(hi) : "l"(v));
}
// d = a * b + d  on packed f32x2 (Blackwell FFMA2, rt_SMSP=2 — verified vs ncu)
__device__ __forceinline__ void fma2(u64& d, u64 a, u64 b) {
    asm("fma.rn.f32x2 %0, %1, %2, %0;" : "+l"(d) : "l"(a), "l"(b));
}
// Streaming (evict-first) 16B store: output is write-once, never re-read.
__device__ __forceinline__ void stg_cs(float* p, float4 v) {
    asm volatile("st.global.cs.v4.f32 [%0], {%1, %2, %3, %4};"
                 :: "l"(p), "f"(v.x), "f"(v.y), "f"(v.z), "f"(v.w) : "memory");
}
// cp.async 16B GMEM -> SMEM (LDGSTS)
__device__ __forceinline__ void cp_async16(void* smem_dst, const void* gmem_src) {
    unsigned saddr = (unsigned)__cvta_generic_to_shared(smem_dst);
    asm volatile("cp.async.cg.shared.global [%0], [%1], 16;"
                 :: "r"(saddr), "l"(gmem_src) : "memory");
}

// Grid: (C=9, B). Block: 192 threads, TARGET 3 blocks/SM (18 warps).
//   q = tid % 48 -> e-quad (e = 4q..4q+3), W for these 4 e rows held in regs
//   g = tid / 48 -> f-group: f = 4g..4g+3, all 16 t each
// t-unroll dropped 2 -> 1 to cut ~30 regs and fit occupancy 3; the L1 cost
// per output (1 broadcast LDS.128 + 1 STG.128 per quad) is UNCHANGED — the
// invariant that round 4's failed occupancy attempt violated.
__global__ __launch_bounds__(192, 3)
void patch_embed_kernel(const float* __restrict__ x,
                        const float* __restrict__ W,
                        const float* __restrict__ bvec,
                        const float* __restrict__ chEmb,
                        const float* __restrict__ spEmb,
                        const float* __restrict__ timePos,
                        const float* __restrict__ freqPos,
                        const int*   __restrict__ spIdx,
                        float* __restrict__ out)
{
    const int c   = blockIdx.x;   // 0..8
    const int b   = blockIdx.y;   // 0..B-1
    const int tid = threadIdx.x;  // 0..191
    const int q   = tid % 48;
    const int g   = tid / 48;     // 0..3
    const int e0  = q * 4;

    __shared__ __align__(16) float xs[BC_FR * BC_T];          // 16 KB input plane
    __shared__ __align__(16) float ws[48 * W_ROW_PAD];        // ~13 KB padded W

    // Stage x plane via cp.async (coalesced 16B, no reg round-trip).
    {
        const float4* gx = reinterpret_cast<const float4*>(
            x + (size_t)(b * BC_C + c) * (BC_FR * BC_T));
        #pragma unroll
        for (int i = tid; i < (BC_FR * BC_T) / 4; i += 192)
            cp_async16(&reinterpret_cast<float4*>(xs)[i], &gx[i]);
    }
    // Stage W (3072 floats) via cp.async into padded smem: global float4 j ->
    // row r = j/16 (e-quad), col = (j%16)*4 within the 64-float row.
    {
        const float4* gw = reinterpret_cast<const float4*>(W);
        #pragma unroll
        for (int j = tid; j < (BC_E * 16) / 4; j += 192) {
            int r   = j >> 4;
            int col = (j & 15) << 2;
            cp_async16(&ws[r * W_ROW_PAD + col], &gw[j]);
        }
    }
    asm volatile("cp.async.commit_group;" ::: "memory");

    // Per-e static bias: b + channel + spatial[spatial_idx[c]] (overlaps cp.async)
    const int sidx = __ldg(spIdx + c);
    float4 bb = *reinterpret_cast<const float4*>(bvec + e0);
    float4 ce = *reinterpret_cast<const float4*>(chEmb + c * BC_E + e0);
    float4 se = *reinterpret_cast<const float4*>(spEmb + sidx * BC_E + e0);
    float4 bs;
    bs.x = bb.x + ce.x + se.x;
    bs.y = bb.y + ce.y + se.y;
    bs.z = bb.z + ce.z + se.z;
    bs.w = bb.w + ce.w + se.w;

    // Per-f base = static + freq_pos[f], for this thread's 4 f values.
    float4 base[4];
    #pragma unroll
    for (int fi = 0; fi < 4; fi++) {
        const int f = g * 4 + fi;
        float4 fe = *reinterpret_cast<const float4*>(freqPos + f * BC_E + e0);
        base[fi].x = bs.x + fe.x;
        base[fi].y = bs.y + fe.y;
        base[fi].z = bs.z + fe.z;
        base[fi].w = bs.w + fe.w;
    }

    asm volatile("cp.async.wait_group 0;" ::: "memory");
    __syncthreads();

    // Pull W for this thread's 4 e rows into regs (conflict-free padded LDS.128).
    u64 w[32];
    #pragma unroll
    for (int i = 0; i < 16; i++) {
        float4 v = *reinterpret_cast<const float4*>(&ws[q * W_ROW_PAD + i * 4]);
        w[2 * i]     = pack2(v.x, v.y);
        w[2 * i + 1] = pack2(v.z, v.w);
    }

    float* outp = out + ((size_t)b * (BC_C * BC_NF * BC_NT)
                         + c * (BC_NF * BC_NT)) * BC_E;

    #pragma unroll 1
    for (int t = 0; t < BC_NT; t++) {
        float4 tp = *reinterpret_cast<const float4*>(timePos + t * BC_E + e0);

        #pragma unroll
        for (int fi = 0; fi < 4; fi++) {
            const int f = g * 4 + fi;

            // Patch x: broadcast LDS (all lanes share (f,t)).
            u64 xp[8];
            #pragma unroll
            for (int u = 0; u < 4; u++) {
                ulonglong2 v = *reinterpret_cast<const ulonglong2*>(
                    &xs[(f * 4 + u) * BC_T + t * 4]);
                xp[2 * u]     = v.x;
                xp[2 * u + 1] = v.y;
            }

            // Accumulator init {base, tp}: lo/hi halves accumulate independent
            // partial sums; final lo+hi folds BOTH biases for free.
            u64 a0 = pack2(base[fi].x, tp.x);
            u64 a1 = pack2(base[fi].y, tp.y);
            u64 a2 = pack2(base[fi].z, tp.z);
            u64 a3 = pack2(base[fi].w, tp.w);

            #pragma unroll
            for (int k = 0; k < 8; k++) {
                fma2(a0, xp[k], w[k]);
                fma2(a1, xp[k], w[8 + k]);
                fma2(a2, xp[k], w[16 + k]);
                fma2(a3, xp[k], w[24 + k]);
            }

            float4 r;
            { float lo, hi; unpack2(a0, lo, hi); r.x = lo + hi; }
            { float lo, hi; unpack2(a1, lo, hi); r.y = lo + hi; }
            { float lo, hi; unpack2(a2, lo, hi); r.z = lo + hi; }
            { float lo, hi; unpack2(a3, lo, hi); r.w = lo + hi; }

            stg_cs(outp + (size_t)(f * BC_NT + t) * BC_E + e0, r);
        }
    }
}

extern "C" void kernel_launch(void* const* d_in, const int* in_sizes, int n_in,
                              void* d_out, int out_size)
{
    const float* x    = (const float*)d_in[0];
    const float* W    = (const float*)d_in[1];
    const float* bv   = (const float*)d_in[2];
    const float* ch   = (const float*)d_in[3];
    const float* sp   = (const float*)d_in[4];
    const float* tpos = (const float*)d_in[5];
    const float* fpos = (const float*)d_in[6];
    const int*   sidx = (const int*)d_in[7];
    float* out = (float*)d_out;

    const int Bx = in_sizes[0] / (BC_C * BC_FR * BC_T);

    dim3 grid(BC_C, Bx);
    patch_embed_kernel<<<grid, 192>>>(x, W, bv, ch, sp, tpos, fpos, sidx, out);
}

// round 8
// speedup vs baseline: 1.0768x; 1.0768x over previous
#include <cuda_runtime.h>

// Problem constants
#define BC_C   9
#define BC_FR  64
#define BC_T   64
#define BC_P   4
#define BC_E   192
#define BC_NF  16
#define BC_NT  16

#define W_ROW_PAD 68   // 64 floats of W per e-quad + 4 pad -> conflict-free LDS.128
#define GRID_P   296   // persistent: 2 blocks/SM x 148 SMs

using u64 = unsigned long long;

__device__ __forceinline__ u64 pack2(float lo, float hi) {
    u64 r;
    asm("mov.b64 %0, {%1, %2};" : "=l"(r) : "f"(lo), "f"(hi));
    return r;
}
__device__ __forceinline__ void unpack2(u64 v, float& lo, float& hi) {
    asm("mov.b64 {%0, %1}, %2;" : "=f"(lo), "=f"(hi) : "l"(v));
}
// d = a * b + d  on packed f32x2 (Blackwell FFMA2, rt_SMSP=2 — verified vs ncu)
__device__ __forceinline__ void fma2(u64& d, u64 a, u64 b) {
    asm("fma.rn.f32x2 %0, %1, %2, %0;" : "+l"(d) : "l"(a), "l"(b));
}
// Streaming (evict-first) 16B store: output is write-once, never re-read.
__device__ __forceinline__ void stg_cs(float* p, float4 v) {
    asm volatile("st.global.cs.v4.f32 [%0], {%1, %2, %3, %4};"
                 :: "l"(p), "f"(v.x), "f"(v.y), "f"(v.z), "f"(v.w) : "memory");
}
// cp.async 16B GMEM -> SMEM (LDGSTS)
__device__ __forceinline__ void cp_async16(void* smem_dst, const void* gmem_src) {
    unsigned saddr = (unsigned)__cvta_generic_to_shared(smem_dst);
    asm volatile("cp.async.cg.shared.global [%0], [%1], 16;"
                 :: "r"(saddr), "l"(gmem_src) : "memory");
}
__device__ __forceinline__ void cp_commit() {
    asm volatile("cp.async.commit_group;" ::: "memory");
}
__device__ __forceinline__ void cp_wait1() {
    asm volatile("cp.async.wait_group 1;" ::: "memory");
}

// PERSISTENT kernel: grid=296 (2 blocks/SM), each block grid-strides over the
// 2304 (b,c) planes. W is staged to smem ONCE per block; the next plane's x
// tile is cp.async-prefetched into the alternate buffer DURING compute, so the
// x DRAM latency and the per-block W restage (which cost ~15 us across the
// old 7.8-wave launch, plus ~9 us of wave transitions) vanish.
// Inner loop is the round-6 optimum unchanged:
//   q = tid % 48 -> e-quad (4 e rows of W in 32 u64 regs)
//   g = tid / 48 -> f-group (4 f), 16 t each; t unrolled by 2.
// (Round-7 lesson: forcing occ 3 spills the 64-reg W array; 12 warps is the
//  layout optimum — we improve overlap, not occupancy.)
__global__ __launch_bounds__(192, 2)
void patch_embed_kernel(const float* __restrict__ x,
                        const float* __restrict__ W,
                        const float* __restrict__ bvec,
                        const float* __restrict__ chEmb,
                        const float* __restrict__ spEmb,
                        const float* __restrict__ timePos,
                        const float* __restrict__ freqPos,
                        const int*   __restrict__ spIdx,
                        float* __restrict__ out,
                        int nPlanes)
{
    const int tid = threadIdx.x;  // 0..191
    const int q   = tid % 48;
    const int g   = tid / 48;     // 0..3
    const int e0  = q * 4;

    __shared__ __align__(16) float xs[2][BC_FR * BC_T];   // 2 x 16 KB x planes
    __shared__ __align__(16) float ws[48 * W_ROW_PAD];    // ~13 KB padded W

    // ---- one-time W stage (group 0, together with first x tile) ----
    {
        const float4* gw = reinterpret_cast<const float4*>(W);
        #pragma unroll
        for (int j = tid; j < (BC_E * 16) / 4; j += 192) {
            int r   = j >> 4;
            int col = (j & 15) << 2;
            cp_async16(&ws[r * W_ROW_PAD + col], &gw[j]);
        }
    }
    int idx0 = blockIdx.x;
    if (idx0 < nPlanes) {
        const float4* gx = reinterpret_cast<const float4*>(
            x + (size_t)idx0 * (BC_FR * BC_T));
        #pragma unroll
        for (int i = tid; i < (BC_FR * BC_T) / 4; i += 192)
            cp_async16(&reinterpret_cast<float4*>(xs[0])[i], &gx[i]);
    }
    cp_commit();   // group: W + x[first]

    u64 w[32];
    bool wLoaded = false;
    int buf = 0;

    for (int idx = idx0; idx < nPlanes; idx += GRID_P) {
        const int c = idx % BC_C;
        const int b = idx / BC_C;

        // Prefetch next plane into the alternate buffer, then commit exactly
        // one group per iteration (possibly empty) to keep wait_group counting.
        const int nxt = idx + GRID_P;
        if (nxt < nPlanes) {
            const float4* gx = reinterpret_cast<const float4*>(
                x + (size_t)nxt * (BC_FR * BC_T));
            #pragma unroll
            for (int i = tid; i < (BC_FR * BC_T) / 4; i += 192)
                cp_async16(&reinterpret_cast<float4*>(xs[buf ^ 1])[i], &gx[i]);
        }
        cp_commit();

        // Per-plane bias math overlaps the in-flight copies.
        const int sidx = __ldg(spIdx + c);
        float4 bb = *reinterpret_cast<const float4*>(bvec + e0);
        float4 ce = *reinterpret_cast<const float4*>(chEmb + c * BC_E + e0);
        float4 se = *reinterpret_cast<const float4*>(spEmb + sidx * BC_E + e0);
        float4 base[4];
        #pragma unroll
        for (int fi = 0; fi < 4; fi++) {
            const int f = g * 4 + fi;
            float4 fe = *reinterpret_cast<const float4*>(freqPos + f * BC_E + e0);
            base[fi].x = bb.x + ce.x + se.x + fe.x;
            base[fi].y = bb.y + ce.y + se.y + fe.y;
            base[fi].z = bb.z + ce.z + se.z + fe.z;
            base[fi].w = bb.w + ce.w + se.w + fe.w;
        }

        cp_wait1();        // current plane's group complete (own thread)
        __syncthreads();   // ... and every thread's copies visible

        if (!wLoaded) {    // uniform branch, first iteration only
            #pragma unroll
            for (int i = 0; i < 16; i++) {
                float4 v = *reinterpret_cast<const float4*>(&ws[q * W_ROW_PAD + i * 4]);
                w[2 * i]     = pack2(v.x, v.y);
                w[2 * i + 1] = pack2(v.z, v.w);
            }
            wLoaded = true;
        }

        const float* xp_s = xs[buf];
        float* outp = out + ((size_t)b * (BC_C * BC_NF * BC_NT)
                             + c * (BC_NF * BC_NT)) * BC_E;

        #pragma unroll 1
        for (int t = 0; t < BC_NT; t += 2) {
            float4 tp0 = *reinterpret_cast<const float4*>(timePos + t * BC_E + e0);
            float4 tp1 = *reinterpret_cast<const float4*>(timePos + (t + 1) * BC_E + e0);

            #pragma unroll
            for (int fi = 0; fi < 4; fi++) {
                const int f = g * 4 + fi;

                u64 xp0[8], xp1[8];
                #pragma unroll
                for (int u = 0; u < 4; u++) {
                    const float* rowp = &xp_s[(f * 4 + u) * BC_T];
                    ulonglong2 v0 = *reinterpret_cast<const ulonglong2*>(rowp + t * 4);
                    ulonglong2 v1 = *reinterpret_cast<const ulonglong2*>(rowp + (t + 1) * 4);
                    xp0[2 * u] = v0.x;  xp0[2 * u + 1] = v0.y;
                    xp1[2 * u] = v1.x;  xp1[2 * u + 1] = v1.y;
                }

                // acc init {base, tp}: lo/hi halves accumulate independently;
                // the final lo+hi folds BOTH biases for free.
                u64 a0 = pack2(base[fi].x, tp0.x);
                u64 a1 = pack2(base[fi].y, tp0.y);
                u64 a2 = pack2(base[fi].z, tp0.z);
                u64 a3 = pack2(base[fi].w, tp0.w);
                u64 b0 = pack2(base[fi].x, tp1.x);
                u64 b1 = pack2(base[fi].y, tp1.y);
                u64 b2 = pack2(base[fi].z, tp1.z);
                u64 b3 = pack2(base[fi].w, tp1.w);

                #pragma unroll
                for (int k = 0; k < 8; k++) {
                    fma2(a0, xp0[k], w[k]);
                    fma2(a1, xp0[k], w[8 + k]);
                    fma2(a2, xp0[k], w[16 + k]);
                    fma2(a3, xp0[k], w[24 + k]);
                    fma2(b0, xp1[k], w[k]);
                    fma2(b1, xp1[k], w[8 + k]);
                    fma2(b2, xp1[k], w[16 + k]);
                    fma2(b3, xp1[k], w[24 + k]);
                }

                float4 r0, r1;
                { float lo, hi; unpack2(a0, lo, hi); r0.x = lo + hi; }
                { float lo, hi; unpack2(a1, lo, hi); r0.y = lo + hi; }
                { float lo, hi; unpack2(a2, lo, hi); r0.z = lo + hi; }
                { float lo, hi; unpack2(a3, lo, hi); r0.w = lo + hi; }
                { float lo, hi; unpack2(b0, lo, hi); r1.x = lo + hi; }
                { float lo, hi; unpack2(b1, lo, hi); r1.y = lo + hi; }
                { float lo, hi; unpack2(b2, lo, hi); r1.z = lo + hi; }
                { float lo, hi; unpack2(b3, lo, hi); r1.w = lo + hi; }

                float* op = outp + (size_t)(f * BC_NT + t) * BC_E + e0;
                stg_cs(op, r0);
                stg_cs(op + BC_E, r1);
            }
        }

        __syncthreads();   // all warps done reading xs[buf] before it is
                           // overwritten by the prefetch two iterations on
        buf ^= 1;
    }
}

extern "C" void kernel_launch(void* const* d_in, const int* in_sizes, int n_in,
                              void* d_out, int out_size)
{
    const float* x    = (const float*)d_in[0];
    const float* W    = (const float*)d_in[1];
    const float* bv   = (const float*)d_in[2];
    const float* ch   = (const float*)d_in[3];
    const float* sp   = (const float*)d_in[4];
    const float* tpos = (const float*)d_in[5];
    const float* fpos = (const float*)d_in[6];
    const int*   sidx = (const int*)d_in[7];
    float* out = (float*)d_out;

    const int Bx = in_sizes[0] / (BC_C * BC_FR * BC_T);
    const int nPlanes = Bx * BC_C;

    int grid = GRID_P < nPlanes ? GRID_P : nPlanes;
    patch_embed_kernel<<<grid, 192>>>(x, W, bv, ch, sp, tpos, fpos, sidx, out, nPlanes);
}

// round 10
// speedup vs baseline: 1.2051x; 1.1191x over previous
#include <cuda_runtime.h>

// Problem constants
#define BC_C   9
#define BC_FR  64
#define BC_T   64
#define BC_P   4
#define BC_E   192
#define BC_NF  16
#define BC_NT  16

#define W_ROW_PAD 68   // 64 floats of W per e-quad + 4 pad -> conflict-free LDS.128

using u64 = unsigned long long;

__device__ __forceinline__ u64 pack2(float lo, float hi) {
    u64 r;
    asm("mov.b64 %0, {%1, %2};" : "=l"(r) : "f"(lo), "f"(hi));
    return r;
}
__device__ __forceinline__ void unpack2(u64 v, float& lo, float& hi) {
    asm("mov.b64 {%0, %1}, %2;" : "=f"(lo), "=f"(hi) : "l"(v));
}
// d = a * b + d  on packed f32x2 (Blackwell FFMA2, rt_SMSP=2 — verified vs ncu)
__device__ __forceinline__ void fma2(u64& d, u64 a, u64 b) {
    asm("fma.rn.f32x2 %0, %1, %2, %0;" : "+l"(d) : "l"(a), "l"(b));
}
// Streaming (evict-first) 16B store: output is write-once, never re-read.
__device__ __forceinline__ void stg_cs(float* p, float4 v) {
    asm volatile("st.global.cs.v4.f32 [%0], {%1, %2, %3, %4};"
                 :: "l"(p), "f"(v.x), "f"(v.y), "f"(v.z), "f"(v.w) : "memory");
}
// cp.async 16B GMEM -> SMEM (LDGSTS)
__device__ __forceinline__ void cp_async16(void* smem_dst, const void* gmem_src) {
    unsigned saddr = (unsigned)__cvta_generic_to_shared(smem_dst);
    asm volatile("cp.async.cg.shared.global [%0], [%1], 16;"
                 :: "r"(saddr), "l"(gmem_src) : "memory");
}

// Grid: (C=9, B). Block: 192 threads, 2 blocks/SM. One block = one (b,c) plane.
//   q = tid % 48 -> e-quad (e = 4q..4q+3), W for these 4 e rows held in regs
//   g = tid / 48 -> f-group: f = 4g..4g+3, all 16 t each
// Design invariants established by rounds 4/7/8:
//   - 4-e layout (1 broadcast LDS.128 + 1 STG.128 per output-quad) is minimum
//     L1 work; e-splitting regresses.
//   - W-in-regs needs 64 regs; forcing occ 3 spills -> 12 warps/SM is optimal.
//   - Classic per-plane blocks beat persistence: wave transitions are cheaper
//     than intra-block barriers (barriers collapse warp skew into stalls).
// This round (re-run; round 9 was an infra failure): t-pair loop at unroll 2
// so ptxas overlaps the next pair's tp-LDG + xp-LDS with the current pair's
// 128-cycle FMA block.
__global__ __launch_bounds__(192, 2)
void patch_embed_kernel(const float* __restrict__ x,
                        const float* __restrict__ W,
                        const float* __restrict__ bvec,
                        const float* __restrict__ chEmb,
                        const float* __restrict__ spEmb,
                        const float* __restrict__ timePos,
                        const float* __restrict__ freqPos,
                        const int*   __restrict__ spIdx,
                        float* __restrict__ out)
{
    const int c   = blockIdx.x;   // 0..8
    const int b   = blockIdx.y;   // 0..B-1
    const int tid = threadIdx.x;  // 0..191
    const int q   = tid % 48;
    const int g   = tid / 48;     // 0..3
    const int e0  = q * 4;

    __shared__ __align__(16) float xs[BC_FR * BC_T];          // 16 KB input plane
    __shared__ __align__(16) float ws[48 * W_ROW_PAD];        // ~13 KB padded W

    // Stage x plane via cp.async (coalesced 16B, no reg round-trip).
    {
        const float4* gx = reinterpret_cast<const float4*>(
            x + (size_t)(b * BC_C + c) * (BC_FR * BC_T));
        #pragma unroll
        for (int i = tid; i < (BC_FR * BC_T) / 4; i += 192)
            cp_async16(&reinterpret_cast<float4*>(xs)[i], &gx[i]);
    }
    // Stage W (3072 floats) via cp.async into padded smem: global float4 j ->
    // row r = j/16 (e-quad), col = (j%16)*4 within the 64-float row.
    {
        const float4* gw = reinterpret_cast<const float4*>(W);
        #pragma unroll
        for (int j = tid; j < (BC_E * 16) / 4; j += 192) {
            int r   = j >> 4;
            int col = (j & 15) << 2;
            cp_async16(&ws[r * W_ROW_PAD + col], &gw[j]);
        }
    }
    asm volatile("cp.async.commit_group;" ::: "memory");

    // Per-e static bias: b + channel + spatial[spatial_idx[c]] (overlaps cp.async)
    const int sidx = __ldg(spIdx + c);
    float4 bb = *reinterpret_cast<const float4*>(bvec + e0);
    float4 ce = *reinterpret_cast<const float4*>(chEmb + c * BC_E + e0);
    float4 se = *reinterpret_cast<const float4*>(spEmb + sidx * BC_E + e0);
    float4 bs;
    bs.x = bb.x + ce.x + se.x;
    bs.y = bb.y + ce.y + se.y;
    bs.z = bb.z + ce.z + se.z;
    bs.w = bb.w + ce.w + se.w;

    // Per-f base = static + freq_pos[f], for this thread's 4 f values.
    float4 base[4];
    #pragma unroll
    for (int fi = 0; fi < 4; fi++) {
        const int f = g * 4 + fi;
        float4 fe = *reinterpret_cast<const float4*>(freqPos + f * BC_E + e0);
        base[fi].x = bs.x + fe.x;
        base[fi].y = bs.y + fe.y;
        base[fi].z = bs.z + fe.z;
        base[fi].w = bs.w + fe.w;
    }

    asm volatile("cp.async.wait_group 0;" ::: "memory");
    __syncthreads();

    // Pull W for this thread's 4 e rows into regs (conflict-free padded LDS.128).
    u64 w[32];
    #pragma unroll
    for (int i = 0; i < 16; i++) {
        float4 v = *reinterpret_cast<const float4*>(&ws[q * W_ROW_PAD + i * 4]);
        w[2 * i]     = pack2(v.x, v.y);
        w[2 * i + 1] = pack2(v.z, v.w);
    }

    float* outp = out + ((size_t)b * (BC_C * BC_NF * BC_NT)
                         + c * (BC_NF * BC_NT)) * BC_E;

    // t-pair loop at unroll 2: lets ptxas overlap the next pair's loads with
    // the current pair's FMA block (unroll 1 forbade cross-iter scheduling).
    #pragma unroll 2
    for (int t = 0; t < BC_NT; t += 2) {
        float4 tp0 = *reinterpret_cast<const float4*>(timePos + t * BC_E + e0);
        float4 tp1 = *reinterpret_cast<const float4*>(timePos + (t + 1) * BC_E + e0);

        #pragma unroll
        for (int fi = 0; fi < 4; fi++) {
            const int f = g * 4 + fi;

            // Patch x for t and t+1: broadcast LDS (all lanes share (f,t)).
            u64 xp0[8], xp1[8];
            #pragma unroll
            for (int u = 0; u < 4; u++) {
                const float* rowp = &xs[(f * 4 + u) * BC_T];
                ulonglong2 v0 = *reinterpret_cast<const ulonglong2*>(rowp + t * 4);
                ulonglong2 v1 = *reinterpret_cast<const ulonglong2*>(rowp + (t + 1) * 4);
                xp0[2 * u] = v0.x;  xp0[2 * u + 1] = v0.y;
                xp1[2 * u] = v1.x;  xp1[2 * u + 1] = v1.y;
            }

            // Accumulator init {base, tp}: lo/hi halves accumulate independent
            // partial sums; the final lo+hi folds BOTH biases for free.
            u64 a0 = pack2(base[fi].x, tp0.x);
            u64 a1 = pack2(base[fi].y, tp0.y);
            u64 a2 = pack2(base[fi].z, tp0.z);
            u64 a3 = pack2(base[fi].w, tp0.w);
            u64 b0 = pack2(base[fi].x, tp1.x);
            u64 b1 = pack2(base[fi].y, tp1.y);
            u64 b2 = pack2(base[fi].z, tp1.z);
            u64 b3 = pack2(base[fi].w, tp1.w);

            #pragma unroll
            for (int k = 0; k < 8; k++) {
                fma2(a0, xp0[k], w[k]);
                fma2(a1, xp0[k], w[8 + k]);
                fma2(a2, xp0[k], w[16 + k]);
                fma2(a3, xp0[k], w[24 + k]);
                fma2(b0, xp1[k], w[k]);
                fma2(b1, xp1[k], w[8 + k]);
                fma2(b2, xp1[k], w[16 + k]);
                fma2(b3, xp1[k], w[24 + k]);
            }

            float4 r0, r1;
            { float lo, hi; unpack2(a0, lo, hi); r0.x = lo + hi; }
            { float lo, hi; unpack2(a1, lo, hi); r0.y = lo + hi; }
            { float lo, hi; unpack2(a2, lo, hi); r0.z = lo + hi; }
            { float lo, hi; unpack2(a3, lo, hi); r0.w = lo + hi; }
            { float lo, hi; unpack2(b0, lo, hi); r1.x = lo + hi; }
            { float lo, hi; unpack2(b1, lo, hi); r1.y = lo + hi; }
            { float lo, hi; unpack2(b2, lo, hi); r1.z = lo + hi; }
            { float lo, hi; unpack2(b3, lo, hi); r1.w = lo + hi; }

            float* op = outp + (size_t)(f * BC_NT + t) * BC_E + e0;
            stg_cs(op, r0);
            stg_cs(op + BC_E, r1);
        }
    }
}

extern "C" void kernel_launch(void* const* d_in, const int* in_sizes, int n_in,
                              void* d_out, int out_size)
{
    const float* x    = (const float*)d_in[0];
    const float* W    = (const float*)d_in[1];
    const float* bv   = (const float*)d_in[2];
    const float* ch   = (const float*)d_in[3];
    const float* sp   = (const float*)d_in[4];
    const float* tpos = (const float*)d_in[5];
    const float* fpos = (const float*)d_in[6];
    const int*   sidx = (const int*)d_in[7];
    float* out = (float*)d_out;

    const int Bx = in_sizes[0] / (BC_C * BC_FR * BC_T);

    dim3 grid(BC_C, Bx);
    patch_embed_kernel<<<grid, 192>>>(x, W, bv, ch, sp, tpos, fpos, sidx, out);
}

// round 11
// speedup vs baseline: 1.3781x; 1.1436x over previous
#include <cuda_runtime.h>

// Problem constants
#define BC_C   9
#define BC_FR  64
#define BC_T   64
#define BC_P   4
#define BC_E   192
#define BC_NF  16
#define BC_NT  16

#define W_ROW_PAD 68   // 64 floats of W per e-quad + 4 pad -> conflict-free LDS.128

using u64 = unsigned long long;

__device__ __forceinline__ u64 pack2(float lo, float hi) {
    u64 r;
    asm("mov.b64 %0, {%1, %2};" : "=l"(r) : "f"(lo), "f"(hi));
    return r;
}
__device__ __forceinline__ void unpack2(u64 v, float& lo, float& hi) {
    asm("mov.b64 {%0, %1}, %2;" : "=f"(lo), "=f"(hi) : "l"(v));
}
// d = a * b + d  on packed f32x2 (Blackwell FFMA2, rt_SMSP=2 — verified vs ncu)
__device__ __forceinline__ void fma2(u64& d, u64 a, u64 b) {
    asm("fma.rn.f32x2 %0, %1, %2, %0;" : "+l"(d) : "l"(a), "l"(b));
}
// Streaming (evict-first) 16B store: output is write-once, never re-read.
__device__ __forceinline__ void stg_cs(float* p, float4 v) {
    asm volatile("st.global.cs.v4.f32 [%0], {%1, %2, %3, %4};"
                 :: "l"(p), "f"(v.x), "f"(v.y), "f"(v.z), "f"(v.w) : "memory");
}
// cp.async 16B GMEM -> SMEM (LDGSTS)
__device__ __forceinline__ void cp_async16(void* smem_dst, const void* gmem_src) {
    unsigned saddr = (unsigned)__cvta_generic_to_shared(smem_dst);
    asm volatile("cp.async.cg.shared.global [%0], [%1], 16;"
                 :: "r"(saddr), "l"(gmem_src) : "memory");
}

// Grid: (C=9, B, 2 f-halves). Block: 96 threads, 4 blocks/SM (same 12 warps/SM
// as round-6 but FOUR independent block contexts: a block's prologue / store
// drain / wave boundary overlaps three running blocks, and RF frees in
// quarter-SM chunks at wave edges).
//   q = tid % 48 -> e-quad (e = 4q..4q+3), W for these 4 e rows held in regs
//   g = tid / 48 -> f-group within the half: f = z*8 + g*4 + fi
// Inner loop is the round-6 optimum byte-for-byte. Invariants from rounds
// 4/7/8/10: 4-e layout = minimum L1 work; W-in-regs needs 64 regs (occ-3 and
// unroll-2 both spill/rematerialize); barriers cost more than wave
// transitions.
__global__ __launch_bounds__(96, 4)
void patch_embed_kernel(const float* __restrict__ x,
                        const float* __restrict__ W,
                        const float* __restrict__ bvec,
                        const float* __restrict__ chEmb,
                        const float* __restrict__ spEmb,
                        const float* __restrict__ timePos,
                        const float* __restrict__ freqPos,
                        const int*   __restrict__ spIdx,
                        float* __restrict__ out)
{
    const int c   = blockIdx.x;   // 0..8
    const int b   = blockIdx.y;   // 0..B-1
    const int z   = blockIdx.z;   // 0..1 (f-half)
    const int tid = threadIdx.x;  // 0..95
    const int q   = tid % 48;
    const int g   = tid / 48;     // 0..1
    const int e0  = q * 4;
    const int f0  = z * 8;        // first f row of this block's half

    __shared__ __align__(16) float xs[(BC_FR / 2) * BC_T];    // 8 KB half-plane
    __shared__ __align__(16) float ws[48 * W_ROW_PAD];        // ~13 KB padded W

    // Stage this half-plane's 32 x-rows via cp.async (coalesced 16B).
    {
        const float4* gx = reinterpret_cast<const float4*>(
            x + ((size_t)(b * BC_C + c) * BC_FR + (size_t)f0 * BC_P) * BC_T);
        #pragma unroll
        for (int i = tid; i < (BC_FR / 2) * BC_T / 4; i += 96)
            cp_async16(&reinterpret_cast<float4*>(xs)[i], &gx[i]);
    }
    // Stage W (3072 floats) via cp.async into padded smem: global float4 j ->
    // row r = j/16 (e-quad), col = (j%16)*4 within the 64-float row.
    {
        const float4* gw = reinterpret_cast<const float4*>(W);
        #pragma unroll
        for (int j = tid; j < (BC_E * 16) / 4; j += 96) {
            int r   = j >> 4;
            int col = (j & 15) << 2;
            cp_async16(&ws[r * W_ROW_PAD + col], &gw[j]);
        }
    }
    asm volatile("cp.async.commit_group;" ::: "memory");

    // Per-e static bias: b + channel + spatial[spatial_idx[c]] (overlaps cp.async)
    const int sidx = __ldg(spIdx + c);
    float4 bb = *reinterpret_cast<const float4*>(bvec + e0);
    float4 ce = *reinterpret_cast<const float4*>(chEmb + c * BC_E + e0);
    float4 se = *reinterpret_cast<const float4*>(spEmb + sidx * BC_E + e0);
    float4 bs;
    bs.x = bb.x + ce.x + se.x;
    bs.y = bb.y + ce.y + se.y;
    bs.z = bb.z + ce.z + se.z;
    bs.w = bb.w + ce.w + se.w;

    // Per-f base = static + freq_pos[f], for this thread's 4 f values.
    float4 base[4];
    #pragma unroll
    for (int fi = 0; fi < 4; fi++) {
        const int f = f0 + g * 4 + fi;
        float4 fe = *reinterpret_cast<const float4*>(freqPos + f * BC_E + e0);
        base[fi].x = bs.x + fe.x;
        base[fi].y = bs.y + fe.y;
        base[fi].z = bs.z + fe.z;
        base[fi].w = bs.w + fe.w;
    }

    asm volatile("cp.async.wait_group 0;" ::: "memory");
    __syncthreads();

    // Pull W for this thread's 4 e rows into regs (conflict-free padded LDS.128).
    u64 w[32];
    #pragma unroll
    for (int i = 0; i < 16; i++) {
        float4 v = *reinterpret_cast<const float4*>(&ws[q * W_ROW_PAD + i * 4]);
        w[2 * i]     = pack2(v.x, v.y);
        w[2 * i + 1] = pack2(v.z, v.w);
    }

    float* outp = out + ((size_t)b * (BC_C * BC_NF * BC_NT)
                         + c * (BC_NF * BC_NT)) * BC_E;

    #pragma unroll 1
    for (int t = 0; t < BC_NT; t += 2) {
        float4 tp0 = *reinterpret_cast<const float4*>(timePos + t * BC_E + e0);
        float4 tp1 = *reinterpret_cast<const float4*>(timePos + (t + 1) * BC_E + e0);

        #pragma unroll
        for (int fi = 0; fi < 4; fi++) {
            const int fl = g * 4 + fi;        // local f row within the half
            const int f  = f0 + fl;           // global f (for output addressing)

            // Patch x for t and t+1: broadcast LDS (all lanes share (f,t)).
            u64 xp0[8], xp1[8];
            #pragma unroll
            for (int u = 0; u < 4; u++) {
                const float* rowp = &xs[(fl * 4 + u) * BC_T];
                ulonglong2 v0 = *reinterpret_cast<const ulonglong2*>(rowp + t * 4);
                ulonglong2 v1 = *reinterpret_cast<const ulonglong2*>(rowp + (t + 1) * 4);
                xp0[2 * u] = v0.x;  xp0[2 * u + 1] = v0.y;
                xp1[2 * u] = v1.x;  xp1[2 * u + 1] = v1.y;
            }

            // Accumulator init {base, tp}: lo/hi halves accumulate independent
            // partial sums; the final lo+hi folds BOTH biases for free.
            u64 a0 = pack2(base[fi].x, tp0.x);
            u64 a1 = pack2(base[fi].y, tp0.y);
            u64 a2 = pack2(base[fi].z, tp0.z);
            u64 a3 = pack2(base[fi].w, tp0.w);
            u64 b0 = pack2(base[fi].x, tp1.x);
            u64 b1 = pack2(base[fi].y, tp1.y);
            u64 b2 = pack2(base[fi].z, tp1.z);
            u64 b3 = pack2(base[fi].w, tp1.w);

            #pragma unroll
            for (int k = 0; k < 8; k++) {
                fma2(a0, xp0[k], w[k]);
                fma2(a1, xp0[k], w[8 + k]);
                fma2(a2, xp0[k], w[16 + k]);
                fma2(a3, xp0[k], w[24 + k]);
                fma2(b0, xp1[k], w[k]);
                fma2(b1, xp1[k], w[8 + k]);
                fma2(b2, xp1[k], w[16 + k]);
                fma2(b3, xp1[k], w[24 + k]);
            }

            float4 r0, r1;
            { float lo, hi; unpack2(a0, lo, hi); r0.x = lo + hi; }
            { float lo, hi; unpack2(a1, lo, hi); r0.y = lo + hi; }
            { float lo, hi; unpack2(a2, lo, hi); r0.z = lo + hi; }
            { float lo, hi; unpack2(a3, lo, hi); r0.w = lo + hi; }
            { float lo, hi; unpack2(b0, lo, hi); r1.x = lo + hi; }
            { float lo, hi; unpack2(b1, lo, hi); r1.y = lo + hi; }
            { float lo, hi; unpack2(b2, lo, hi); r1.z = lo + hi; }
            { float lo, hi; unpack2(b3, lo, hi); r1.w = lo + hi; }

            float* op = outp + (size_t)(f * BC_NT + t) * BC_E + e0;
            stg_cs(op, r0);
            stg_cs(op + BC_E, r1);
        }
    }
}

extern "C" void kernel_launch(void* const* d_in, const int* in_sizes, int n_in,
                              void* d_out, int out_size)
{
    const float* x    = (const float*)d_in[0];
    const float* W    = (const float*)d_in[1];
    const float* bv   = (const float*)d_in[2];
    const float* ch   = (const float*)d_in[3];
    const float* sp   = (const float*)d_in[4];
    const float* tpos = (const float*)d_in[5];
    const float* fpos = (const float*)d_in[6];
    const int*   sidx = (const int*)d_in[7];
    float* out = (float*)d_out;

    const int Bx = in_sizes[0] / (BC_C * BC_FR * BC_T);

    dim3 grid(BC_C, Bx, 2);
    patch_embed_kernel<<<grid, 96>>>(x, W, bv, ch, sp, tpos, fpos, sidx, out);
}

// round 12
// speedup vs baseline: 1.3791x; 1.0007x over previous
#include <cuda_runtime.h>

// Problem constants
#define BC_C   9
#define BC_FR  64
#define BC_T   64
#define BC_P   4
#define BC_E   192
#define BC_NF  16
#define BC_NT  16

#define W_ROW_PAD 68   // 64 floats of W per e-quad + 4 pad -> conflict-free LDS.128

using u64 = unsigned long long;

__device__ __forceinline__ u64 pack2(float lo, float hi) {
    u64 r;
    asm("mov.b64 %0, {%1, %2};" : "=l"(r) : "f"(lo), "f"(hi));
    return r;
}
__device__ __forceinline__ void unpack2(u64 v, float& lo, float& hi) {
    asm("mov.b64 {%0, %1}, %2;" : "=f"(lo), "=f"(hi) : "l"(v));
}
// d = a * b + d  on packed f32x2 (Blackwell FFMA2, rt_SMSP=2 — verified vs ncu)
__device__ __forceinline__ void fma2(u64& d, u64 a, u64 b) {
    asm("fma.rn.f32x2 %0, %1, %2, %0;" : "+l"(d) : "l"(a), "l"(b));
}
// Streaming (evict-first) 16B store: output is write-once, never re-read.
__device__ __forceinline__ void stg_cs(float* p, float4 v) {
    asm volatile("st.global.cs.v4.f32 [%0], {%1, %2, %3, %4};"
                 :: "l"(p), "f"(v.x), "f"(v.y), "f"(v.z), "f"(v.w) : "memory");
}
// cp.async 16B GMEM -> SMEM (LDGSTS)
__device__ __forceinline__ void cp_async16(void* smem_dst, const void* gmem_src) {
    unsigned saddr = (unsigned)__cvta_generic_to_shared(smem_dst);
    asm volatile("cp.async.cg.shared.global [%0], [%1], 16;"
                 :: "r"(saddr), "l"(gmem_src) : "memory");
}

// Grid: (C=9, B, 2 f-halves). Block: 96 threads, 4 blocks/SM (12 warps/SM in
// four independent contexts — round-11 win: prologue/drain/wave stalls of one
// block hide under the other three).
//   q = tid % 48 -> e-quad (e = 4q..4q+3), W for these 4 e rows held in regs
//   g = tid / 48 -> f-group within the half: f = z*8 + g*4 + fi
// Round-12 deltas: (1) timePos staged to smem — hot-loop tp reads leave the
// LDG/L1 path; (2) two cp.async groups — W register pull overlaps the x
// tile's DRAM latency instead of waiting for it.
// Invariants (rounds 4/7/8/10): 4-e layout = min L1 work; W-in-regs needs 64
// regs (occ-3 / unroll-2 spill); barriers cost more than wave transitions.
__global__ __launch_bounds__(96, 4)
void patch_embed_kernel(const float* __restrict__ x,
                        const float* __restrict__ W,
                        const float* __restrict__ bvec,
                        const float* __restrict__ chEmb,
                        const float* __restrict__ spEmb,
                        const float* __restrict__ timePos,
                        const float* __restrict__ freqPos,
                        const int*   __restrict__ spIdx,
                        float* __restrict__ out)
{
    const int c   = blockIdx.x;   // 0..8
    const int b   = blockIdx.y;   // 0..B-1
    const int z   = blockIdx.z;   // 0..1 (f-half)
    const int tid = threadIdx.x;  // 0..95
    const int q   = tid % 48;
    const int g   = tid / 48;     // 0..1
    const int e0  = q * 4;
    const int f0  = z * 8;        // first f row of this block's half

    __shared__ __align__(16) float xs[(BC_FR / 2) * BC_T];    // 8 KB half-plane
    __shared__ __align__(16) float ws[48 * W_ROW_PAD];        // ~13 KB padded W
    __shared__ __align__(16) float tps[BC_NT * BC_E];         // 12 KB timePos

    // ---- group 1: W + timePos (small, L2-hot after first blocks) ----
    {
        const float4* gw = reinterpret_cast<const float4*>(W);
        #pragma unroll
        for (int j = tid; j < (BC_E * 16) / 4; j += 96) {
            int r   = j >> 4;
            int col = (j & 15) << 2;
            cp_async16(&ws[r * W_ROW_PAD + col], &gw[j]);
        }
        const float4* gt = reinterpret_cast<const float4*>(timePos);
        #pragma unroll
        for (int j = tid; j < (BC_NT * BC_E) / 4; j += 96)
            cp_async16(&reinterpret_cast<float4*>(tps)[j], &gt[j]);
    }
    asm volatile("cp.async.commit_group;" ::: "memory");

    // ---- group 2: this half-plane's 32 x-rows ----
    {
        const float4* gx = reinterpret_cast<const float4*>(
            x + ((size_t)(b * BC_C + c) * BC_FR + (size_t)f0 * BC_P) * BC_T);
        #pragma unroll
        for (int i = tid; i < (BC_FR / 2) * BC_T / 4; i += 96)
            cp_async16(&reinterpret_cast<float4*>(xs)[i], &gx[i]);
    }
    asm volatile("cp.async.commit_group;" ::: "memory");

    // Per-e static bias: b + channel + spatial[spatial_idx[c]] (overlaps copies)
    const int sidx = __ldg(spIdx + c);
    float4 bb = *reinterpret_cast<const float4*>(bvec + e0);
    float4 ce = *reinterpret_cast<const float4*>(chEmb + c * BC_E + e0);
    float4 se = *reinterpret_cast<const float4*>(spEmb + sidx * BC_E + e0);
    float4 bs;
    bs.x = bb.x + ce.x + se.x;
    bs.y = bb.y + ce.y + se.y;
    bs.z = bb.z + ce.z + se.z;
    bs.w = bb.w + ce.w + se.w;

    // Per-f base = static + freq_pos[f], for this thread's 4 f values.
    float4 base[4];
    #pragma unroll
    for (int fi = 0; fi < 4; fi++) {
        const int f = f0 + g * 4 + fi;
        float4 fe = *reinterpret_cast<const float4*>(freqPos + f * BC_E + e0);
        base[fi].x = bs.x + fe.x;
        base[fi].y = bs.y + fe.y;
        base[fi].z = bs.z + fe.z;
        base[fi].w = bs.w + fe.w;
    }

    // Wait group 1 only (W + tp): pull W into regs while x is still in flight.
    asm volatile("cp.async.wait_group 1;" ::: "memory");
    __syncthreads();

    // Pull W for this thread's 4 e rows into regs (conflict-free padded LDS.128).
    u64 w[32];
    #pragma unroll
    for (int i = 0; i < 16; i++) {
        float4 v = *reinterpret_cast<const float4*>(&ws[q * W_ROW_PAD + i * 4]);
        w[2 * i]     = pack2(v.x, v.y);
        w[2 * i + 1] = pack2(v.z, v.w);
    }

    // Now wait for the x tile.
    asm volatile("cp.async.wait_group 0;" ::: "memory");
    __syncthreads();

    float* outp = out + ((size_t)b * (BC_C * BC_NF * BC_NT)
                         + c * (BC_NF * BC_NT)) * BC_E;

    #pragma unroll 1
    for (int t = 0; t < BC_NT; t += 2) {
        // tp from smem: lane q reads tps[t*192 + 4q] -> banks 4q mod 32,
        // distinct per 8-lane phase -> conflict-free LDS.128.
        float4 tp0 = *reinterpret_cast<const float4*>(&tps[t * BC_E + e0]);
        float4 tp1 = *reinterpret_cast<const float4*>(&tps[(t + 1) * BC_E + e0]);

        #pragma unroll
        for (int fi = 0; fi < 4; fi++) {
            const int fl = g * 4 + fi;        // local f row within the half
            const int f  = f0 + fl;           // global f (output addressing)

            // Patch x for t and t+1: broadcast LDS (all lanes share (f,t)).
            u64 xp0[8], xp1[8];
            #pragma unroll
            for (int u = 0; u < 4; u++) {
                const float* rowp = &xs[(fl * 4 + u) * BC_T];
                ulonglong2 v0 = *reinterpret_cast<const ulonglong2*>(rowp + t * 4);
                ulonglong2 v1 = *reinterpret_cast<const ulonglong2*>(rowp + (t + 1) * 4);
                xp0[2 * u] = v0.x;  xp0[2 * u + 1] = v0.y;
                xp1[2 * u] = v1.x;  xp1[2 * u + 1] = v1.y;
            }

            // Accumulator init {base, tp}: lo/hi halves accumulate independent
            // partial sums; the final lo+hi folds BOTH biases for free.
            u64 a0 = pack2(base[fi].x, tp0.x);
            u64 a1 = pack2(base[fi].y, tp0.y);
            u64 a2 = pack2(base[fi].z, tp0.z);
            u64 a3 = pack2(base[fi].w, tp0.w);
            u64 b0 = pack2(base[fi].x, tp1.x);
            u64 b1 = pack2(base[fi].y, tp1.y);
            u64 b2 = pack2(base[fi].z, tp1.z);
            u64 b3 = pack2(base[fi].w, tp1.w);

            #pragma unroll
            for (int k = 0; k < 8; k++) {
                fma2(a0, xp0[k], w[k]);
                fma2(a1, xp0[k], w[8 + k]);
                fma2(a2, xp0[k], w[16 + k]);
                fma2(a3, xp0[k], w[24 + k]);
                fma2(b0, xp1[k], w[k]);
                fma2(b1, xp1[k], w[8 + k]);
                fma2(b2, xp1[k], w[16 + k]);
                fma2(b3, xp1[k], w[24 + k]);
            }

            float4 r0, r1;
            { float lo, hi; unpack2(a0, lo, hi); r0.x = lo + hi; }
            { float lo, hi; unpack2(a1, lo, hi); r0.y = lo + hi; }
            { float lo, hi; unpack2(a2, lo, hi); r0.z = lo + hi; }
            { float lo, hi; unpack2(a3, lo, hi); r0.w = lo + hi; }
            { float lo, hi; unpack2(b0, lo, hi); r1.x = lo + hi; }
            { float lo, hi; unpack2(b1, lo, hi); r1.y = lo + hi; }
            { float lo, hi; unpack2(b2, lo, hi); r1.z = lo + hi; }
            { float lo, hi; unpack2(b3, lo, hi); r1.w = lo + hi; }

            float* op = outp + (size_t)(f * BC_NT + t) * BC_E + e0;
            stg_cs(op, r0);
            stg_cs(op + BC_E, r1);
        }
    }
}

extern "C" void kernel_launch(void* const* d_in, const int* in_sizes, int n_in,
                              void* d_out, int out_size)
{
    const float* x    = (const float*)d_in[0];
    const float* W    = (const float*)d_in[1];
    const float* bv   = (const float*)d_in[2];
    const float* ch   = (const float*)d_in[3];
    const float* sp   = (const float*)d_in[4];
    const float* tpos = (const float*)d_in[5];
    const float* fpos = (const float*)d_in[6];
    const int*   sidx = (const int*)d_in[7];
    float* out = (float*)d_out;

    const int Bx = in_sizes[0] / (BC_C * BC_FR * BC_T);

    dim3 grid(BC_C, Bx, 2);
    patch_embed_kernel<<<grid, 96>>>(x, W, bv, ch, sp, tpos, fpos, sidx, out);
}